// round 15
// baseline (speedup 1.0000x reference)
#include <cuda_runtime.h>
#include <cuda_fp16.h>
#include <math.h>
#include <float.h>

#define NN 20000
#define EE 320000
#define MM 3
#define FIN 128
#define HH 4
#define CC 64
#define NEG_SLOPE 0.2f

// ---------------- scratch (device globals) ----------------
__device__ __align__(16) __half g_h[MM * NN * HH * CC];    // projected features (fp16)
__device__ __align__(16) float g_asrc[MM * NN * HH];
__device__ __align__(16) float g_adst[MM * NN * HH];
__device__ __align__(16) float g_zstack[NN * MM * CC];
__device__ __align__(16) float g_hout[NN * CC];
__device__ float g_stats[MM * 2];                           // per m: sum, sumsq (raw only)
__device__ __align__(16) float g_edot1[MM * HH];            // layer-1 per-head edge scalars
__device__ float g_edot2[MM];                               // layer-2 edge scalars
__device__ float g_aff1[MM * 2];                            // layer-1 BN scale/shift
__device__ float g_aff2[MM * 2];                            // layer-2 BN scale/shift
// CSR: payload packed {src, log1p(attr)} in CSR order
__device__ int   g_deg[MM * NN];
__device__ int   g_rowptr[MM * (NN + 1)];
__device__ int   g_cursor[MM * NN];
__device__ float g_lea[MM * EE];                            // log1p(attr), edge order
__device__ __align__(8) int2 g_sl[MM * EE];                 // {src, bitcast lea}, CSR order

// ---------------- helpers ----------------
__device__ __forceinline__ float elu1(float x) { return x > 0.f ? x : expm1f(x); }
__device__ __forceinline__ float lrelu_exp(float a) {
    a = a > 0.f ? a : NEG_SLOPE * a;
    return expf(a);
}
__device__ __forceinline__ unsigned pack2(float a, float b) {
    __half2 h = __float22half2_rn(make_float2(a, b));
    return *(unsigned*)&h;
}
__device__ __forceinline__ float2 up2(unsigned u) {
    return __half22float2(*(__half2*)&u);
}

// ---------------- zero init ----------------
__global__ void k_zero1() {
    int i = blockIdx.x * blockDim.x + threadIdx.x;
    if (i < MM * NN) g_deg[i] = 0;
    if (i < MM * 2) g_stats[i] = 0.f;
}

// ---------------- fused: degree histogram + log1p + BN stats ----------------
__global__ void k_build(const int* __restrict__ ei_all, const float* __restrict__ attr) {
    int m = blockIdx.y;
    int e = blockIdx.x * 256 + threadIdx.x;
    float v = 0.f, v2 = 0.f;
    if (e < EE) {
        atomicAdd(&g_deg[m * NN + ei_all[m * 2 * EE + EE + e]], 1);
        float t = log1pf(attr[m * EE + e]);
        g_lea[(size_t)m * EE + e] = t;
        v = t; v2 = t * t;
    }
#pragma unroll
    for (int o = 16; o; o >>= 1) {
        v  += __shfl_down_sync(0xffffffffu, v,  o);
        v2 += __shfl_down_sync(0xffffffffu, v2, o);
    }
    __shared__ float s1[8], s2[8];
    int lane = threadIdx.x & 31, w = threadIdx.x >> 5;
    if (lane == 0) { s1[w] = v; s2[w] = v2; }
    __syncthreads();
    if (threadIdx.x == 0) {
        float a = 0.f, b = 0.f;
        for (int j = 0; j < 8; j++) { a += s1[j]; b += s2[j]; }
        atomicAdd(&g_stats[m * 2 + 0], a);
        atomicAdd(&g_stats[m * 2 + 1], b);
    }
}

// ---------------- CSR: exclusive scan (one block per metapath) ----------------
__global__ void k_scan() {
    int m = blockIdx.x;
    __shared__ int swarp[32];
    int tid = threadIdx.x, lane = tid & 31, w = tid >> 5;
    int carry = 0;
    if (tid == 0) g_rowptr[m * (NN + 1)] = 0;
    for (int c0 = 0; c0 < NN; c0 += 1024) {
        int i = c0 + tid;
        int v = (i < NN) ? g_deg[m * NN + i] : 0;
        int incl = v;
#pragma unroll
        for (int off = 1; off < 32; off <<= 1) {
            int t = __shfl_up_sync(0xffffffffu, incl, off);
            if (lane >= off) incl += t;
        }
        if (lane == 31) swarp[w] = incl;
        __syncthreads();
        if (w == 0) {
            int x = swarp[lane];
#pragma unroll
            for (int off = 1; off < 32; off <<= 1) {
                int t = __shfl_up_sync(0xffffffffu, x, off);
                if (lane >= off) x += t;
            }
            swarp[lane] = x;
        }
        __syncthreads();
        int offset = (w > 0) ? swarp[w - 1] : 0;
        int total = swarp[31];
        incl += offset;
        if (i < NN) {
            g_rowptr[m * (NN + 1) + i + 1] = carry + incl;
            g_cursor[m * NN + i] = carry + incl - v;
        }
        carry += total;
        __syncthreads();
    }
}

// ---------------- CSR: scatter packed payload ----------------
__global__ void k_scatter(const int* __restrict__ ei_all) {
    int e = blockIdx.x * 256 + threadIdx.x;
    if (e >= EE) return;
    int m = blockIdx.y;
    int s = ei_all[m * 2 * EE + e];
    int d = ei_all[m * 2 * EE + EE + e];
    int pos = atomicAdd(&g_cursor[m * NN + d], 1);
    g_sl[(size_t)m * EE + pos] = make_int2(s, __float_as_int(g_lea[(size_t)m * EE + e]));
}

// ---------------- finalize BN affine + per-head edge scalar (de-aliased) -------
template<int H, int C>
__global__ void k_bnfin(const float* __restrict__ lew, const float* __restrict__ aew,
                        const float* __restrict__ gamma, const float* __restrict__ beta,
                        float* __restrict__ edot_out, float* __restrict__ aff_out) {
    int w = threadIdx.x >> 5, lane = threadIdx.x & 31;   // MM*H warps
    int m = w / H, h = w % H;
    float s = 0.f;
    for (int c = lane; c < C; c += 32)
        s += lew[(m * H + h) * C + c] * aew[(m * H + h) * C + c];
#pragma unroll
    for (int o = 16; o; o >>= 1) s += __shfl_down_sync(0xffffffffu, s, o);
    if (lane == 0) edot_out[m * H + h] = s;
    if (threadIdx.x < MM) {
        int mm = threadIdx.x;
        float mu   = g_stats[mm * 2 + 0] * (1.f / EE);
        float var  = g_stats[mm * 2 + 1] * (1.f / EE) - mu * mu;
        float sc   = gamma[mm] * rsqrtf(var + 1e-5f);
        aff_out[mm * 2 + 0] = sc;
        aff_out[mm * 2 + 1] = beta[mm] - mu * sc;
    }
}

// ---------------- layer-1 SGEMM: 128x128 tile, 8x8 microtile, fp16 h store -----
template<int K, int NC, int H>
__global__ void __launch_bounds__(256, 2) k_sgemm1(
        const float* __restrict__ X, const float* __restrict__ Wall,
        const float* __restrict__ asw, const float* __restrict__ adw) {
    __shared__ float Xs[128][33];
    __shared__ float Ws[32][128];
    int m = blockIdx.z;
    const float* W = Wall + (size_t)m * K * NC;
    __half* Hd = g_h + (size_t)m * NN * NC;
    int nb = blockIdx.y * 128, cb = blockIdx.x * 128;
    int tid = threadIdx.x, tx = tid & 15, ty = tid >> 4;
    float acc[8][8];
#pragma unroll
    for (int i = 0; i < 8; i++)
#pragma unroll
        for (int j = 0; j < 8; j++) acc[i][j] = 0.f;

    for (int kt = 0; kt < K; kt += 32) {
#pragma unroll
        for (int i = 0; i < 4; i++) {
            int v = tid + i * 256;
            int row = v >> 3, kq = (v & 7) << 2;
            int gr = nb + row;
            float4 xv = make_float4(0.f, 0.f, 0.f, 0.f);
            if (gr < NN) xv = *(const float4*)(X + (size_t)gr * K + kt + kq);
            Xs[row][kq + 0] = xv.x; Xs[row][kq + 1] = xv.y;
            Xs[row][kq + 2] = xv.z; Xs[row][kq + 3] = xv.w;
        }
#pragma unroll
        for (int i = 0; i < 4; i++) {
            int v = tid + i * 256;
            int kr = v >> 5, cq = (v & 31) << 2;
            *(float4*)&Ws[kr][cq] = *(const float4*)(W + (size_t)(kt + kr) * NC + cb + cq);
        }
        __syncthreads();
#pragma unroll 4
        for (int k = 0; k < 32; k++) {
            float a[8];
#pragma unroll
            for (int i = 0; i < 8; i++) a[i] = Xs[ty * 8 + i][k];
            float b[8];
            float4 b0 = *(float4*)&Ws[k][tx * 8];
            float4 b1 = *(float4*)&Ws[k][tx * 8 + 4];
            b[0] = b0.x; b[1] = b0.y; b[2] = b0.z; b[3] = b0.w;
            b[4] = b1.x; b[5] = b1.y; b[6] = b1.z; b[7] = b1.w;
#pragma unroll
            for (int i = 0; i < 8; i++)
#pragma unroll
                for (int j = 0; j < 8; j++) acc[i][j] += a[i] * b[j];
        }
        __syncthreads();
    }
#pragma unroll
    for (int i = 0; i < 8; i++) {
        int gr = nb + ty * 8 + i;
        if (gr < NN) {
            uint4 pk;
            pk.x = pack2(acc[i][0], acc[i][1]);
            pk.y = pack2(acc[i][2], acc[i][3]);
            pk.z = pack2(acc[i][4], acc[i][5]);
            pk.w = pack2(acc[i][6], acc[i][7]);
            *(uint4*)(Hd + (size_t)gr * NC + cb + tx * 8) = pk;
        }
    }
    int colbase = cb + tx * 8;
    int head = colbase >> 6;
#pragma unroll
    for (int i = 0; i < 8; i++) {
        float ps = 0.f, pd = 0.f;
#pragma unroll
        for (int j = 0; j < 8; j++) {
            ps += acc[i][j] * asw[m * H * 64 + colbase + j];
            pd += acc[i][j] * adw[m * H * 64 + colbase + j];
        }
        ps += __shfl_down_sync(0xffffffffu, ps, 4, 8);
        pd += __shfl_down_sync(0xffffffffu, pd, 4, 8);
        ps += __shfl_down_sync(0xffffffffu, ps, 2, 8);
        pd += __shfl_down_sync(0xffffffffu, pd, 2, 8);
        ps += __shfl_down_sync(0xffffffffu, ps, 1, 8);
        pd += __shfl_down_sync(0xffffffffu, pd, 1, 8);
        int gr = nb + ty * 8 + i;
        if ((tx & 7) == 0 && gr < NN) {
            g_asrc[(size_t)(m * NN + gr) * H + head] = ps;
            g_adst[(size_t)(m * NN + gr) * H + head] = pd;
        }
    }
}

// ---------------- layer-2 SGEMM (64 cols) ----------------
template<int K, int NC, int CT, int H>
__global__ void k_sgemm(const float* __restrict__ X, const float* __restrict__ Wall,
                        const float* __restrict__ asw, const float* __restrict__ adw) {
    constexpr int CP = CT / 16;
    constexpr int RW = 64 / CP;
    extern __shared__ float sm[];
    float* Xs = sm;                  // [64][68]
    float* Ws = sm + 64 * 68;        // [64][CT]
    int m = blockIdx.z;
    const float* W = Wall + (size_t)m * K * NC;
    __half* Hd = g_h + (size_t)m * NN * NC;
    int nb = blockIdx.y * 64, cb = blockIdx.x * CT;
    int tid = threadIdx.x, tx = tid & 15, ty = tid >> 4;
    float acc[4][CP];
#pragma unroll
    for (int i = 0; i < 4; i++)
#pragma unroll
        for (int j = 0; j < CP; j++) acc[i][j] = 0.f;

    for (int kt = 0; kt < K; kt += 64) {
#pragma unroll
        for (int i = 0; i < 4; i++) {
            int v = tid + i * 256;
            int row = v >> 4, kq = (v & 15) << 2;
            int gr = nb + row;
            float4 xv = make_float4(0.f, 0.f, 0.f, 0.f);
            if (gr < NN) xv = *(const float4*)(X + (size_t)gr * K + kt + kq);
            *(float4*)&Xs[row * 68 + kq] = xv;
        }
#pragma unroll
        for (int i = 0; i < CP; i++) {
            int v = tid + i * 256;
            int krow = v / (CT / 4), cq = (v % (CT / 4)) * 4;
            *(float4*)&Ws[krow * CT + cq] = *(const float4*)(W + (size_t)(kt + krow) * NC + cb + cq);
        }
        __syncthreads();
#pragma unroll 8
        for (int k = 0; k < 64; k++) {
            float a[4];
#pragma unroll
            for (int i = 0; i < 4; i++) a[i] = Xs[(ty * 4 + i) * 68 + k];
            float b[CP];
#pragma unroll
            for (int jj = 0; jj < CP / 4; jj++) {
                float4 bv = *(float4*)&Ws[k * CT + tx * CP + 4 * jj];
                b[4 * jj + 0] = bv.x; b[4 * jj + 1] = bv.y;
                b[4 * jj + 2] = bv.z; b[4 * jj + 3] = bv.w;
            }
#pragma unroll
            for (int i = 0; i < 4; i++)
#pragma unroll
                for (int j = 0; j < CP; j++) acc[i][j] += a[i] * b[j];
        }
        __syncthreads();
    }
#pragma unroll
    for (int i = 0; i < 4; i++) {
        int gr = nb + ty * 4 + i;
        if (gr < NN) {
            uint2 pk;
            pk.x = pack2(acc[i][0], acc[i][1]);
            pk.y = pack2(acc[i][2], acc[i][3]);
            *(uint2*)(Hd + (size_t)gr * NC + cb + tx * CP) = pk;
        }
    }
    int colbase = cb + tx * CP;
    int head = colbase / 64;
#pragma unroll
    for (int i = 0; i < 4; i++) {
        float ps = 0.f, pd = 0.f;
#pragma unroll
        for (int j = 0; j < CP; j++) {
            ps += acc[i][j] * asw[m * H * 64 + colbase + j];
            pd += acc[i][j] * adw[m * H * 64 + colbase + j];
        }
#pragma unroll
        for (int off = RW / 2; off; off >>= 1) {
            ps += __shfl_down_sync(0xffffffffu, ps, off, RW);
            pd += __shfl_down_sync(0xffffffffu, pd, off, RW);
        }
        int gr = nb + ty * 4 + i;
        if ((tx & (RW - 1)) == 0 && gr < NN) {
            g_asrc[(size_t)(m * NN + gr) * H + head] = ps;
            g_adst[(size_t)(m * NN + gr) * H + head] = pd;
        }
    }
}

// ---------------- GAT layer 1 (H=4): smem-free, single-phase, fp16 gathers ----
// one warp per node; lane l: head h=l>>3, uint4 channel block l (8 fp16).
// per edge: broadcast {src,lea}, scalar asrc[src*4+h], one exp per lane,
// one uint4 gather + 8 FMA. No smem, no syncwarp, iterations independent.
__global__ void k_gat4(const float* __restrict__ bias) {
    int w = threadIdx.x >> 5, l = threadIdx.x & 31;
    int m = blockIdx.y;
    int n = blockIdx.x * 8 + w;                 // grid.x = NN/8 exact
    int base = g_rowptr[m * (NN + 1) + n];
    int deg  = g_rowptr[m * (NN + 1) + n + 1] - base;
    float sc = g_aff1[m * 2 + 0], sh = g_aff1[m * 2 + 1];
    int h = l >> 3;
    float edot_h = g_edot1[m * 4 + h];
    float adst_h = g_adst[(size_t)(m * NN + n) * 4 + h];
    const int2* slp = g_sl + (size_t)m * EE + base;
    const uint4* hb = (const uint4*)(g_h + (size_t)m * NN * 256);   // 32 uint4/node
    const float* asp = g_asrc + (size_t)m * NN * 4;
    float acc[8] = {};
    float den = 0.f;

#pragma unroll 2
    for (int j = 0; j < deg; j++) {
        int2 sl = slp[j];
        float ea = __int_as_float(sl.y) * sc + sh;
        float as = asp[(size_t)sl.x * 4 + h];
        float wt = lrelu_exp(as + adst_h + ea * edot_h);
        uint4 hv = hb[(size_t)sl.x * 32 + l];
        float2 f;
        f = up2(hv.x); acc[0] += wt * f.x; acc[1] += wt * f.y;
        f = up2(hv.y); acc[2] += wt * f.x; acc[3] += wt * f.y;
        f = up2(hv.z); acc[4] += wt * f.x; acc[5] += wt * f.y;
        f = up2(hv.w); acc[6] += wt * f.x; acc[7] += wt * f.y;
        den += wt;
    }

    // per-head normalize (den uniform within each 8-lane head group), head-sum
    float inv = 1.f / (den + 1e-16f);
#pragma unroll
    for (int k = 0; k < 8; k++) {
        float v = acc[k] * inv;
        v += __shfl_down_sync(0xffffffffu, v, 8);
        v += __shfl_down_sync(0xffffffffu, v, 16);
        acc[k] = v;
    }
    if (l < 8) {
        const float* bp = bias + m * 64 + 8 * l;
        float4 r0, r1;
        r0.x = elu1(acc[0] * 0.25f + bp[0]); r0.y = elu1(acc[1] * 0.25f + bp[1]);
        r0.z = elu1(acc[2] * 0.25f + bp[2]); r0.w = elu1(acc[3] * 0.25f + bp[3]);
        r1.x = elu1(acc[4] * 0.25f + bp[4]); r1.y = elu1(acc[5] * 0.25f + bp[5]);
        r1.z = elu1(acc[6] * 0.25f + bp[6]); r1.w = elu1(acc[7] * 0.25f + bp[7]);
        float* zp = &g_zstack[((size_t)n * MM + m) * 64 + 8 * l];
        *(float4*)zp = r0;
        *(float4*)(zp + 4) = r1;
    }
}

// ---------------- GAT layer 2 (H=1): 8 lanes/node, fp16, no smem/syncs --------
__global__ void k_gat1(const float* __restrict__ bias) {
    int tid = threadIdx.x;
    int g = tid >> 3, l8 = tid & 7;
    int m = blockIdx.y;
    int n = blockIdx.x * 32 + g;                // grid.x = NN/32 exact
    int base = g_rowptr[m * (NN + 1) + n];
    int deg  = g_rowptr[m * (NN + 1) + n + 1] - base;
    float sc = g_aff2[m * 2 + 0], sh = g_aff2[m * 2 + 1];
    float edot = g_edot2[m];
    float adst = g_adst[m * NN + n];
    const int2* slp = g_sl + (size_t)m * EE + base;
    const uint4* hb = (const uint4*)(g_h + (size_t)m * NN * 64);    // 8 uint4/node
    const float* asp = g_asrc + (size_t)m * NN;
    float acc[8] = {};
    float den = 0.f;

#pragma unroll 2
    for (int j = 0; j < deg; j++) {
        int2 sl = slp[j];
        float ea = __int_as_float(sl.y) * sc + sh;
        float wt = lrelu_exp(asp[sl.x] + adst + ea * edot);
        uint4 hv = hb[(size_t)sl.x * 8 + l8];
        float2 f;
        f = up2(hv.x); acc[0] += wt * f.x; acc[1] += wt * f.y;
        f = up2(hv.y); acc[2] += wt * f.x; acc[3] += wt * f.y;
        f = up2(hv.z); acc[4] += wt * f.x; acc[5] += wt * f.y;
        f = up2(hv.w); acc[6] += wt * f.x; acc[7] += wt * f.y;
        den += wt;
    }
    float inv = 1.f / (den + 1e-16f);
    const float* bp = bias + m * 64 + 8 * l8;
    float4 r0, r1;
    r0.x = elu1(acc[0] * inv + bp[0]); r0.y = elu1(acc[1] * inv + bp[1]);
    r0.z = elu1(acc[2] * inv + bp[2]); r0.w = elu1(acc[3] * inv + bp[3]);
    r1.x = elu1(acc[4] * inv + bp[4]); r1.y = elu1(acc[5] * inv + bp[5]);
    r1.z = elu1(acc[6] * inv + bp[6]); r1.w = elu1(acc[7] * inv + bp[7]);
    float* zp = &g_zstack[((size_t)n * MM + m) * 64 + 8 * l8];
    *(float4*)zp = r0;
    *(float4*)(zp + 4) = r1;
}

// ---------------- semantic attention over M (4 nodes per block) ----------------
__global__ void k_semantic(const float* __restrict__ semw, const float* __restrict__ semb,
                           const float* __restrict__ semv,
                           float* __restrict__ out, float* beta_out) {
    __shared__ float zsh[4][MM][CC];
    __shared__ float wred[4][2];
    __shared__ float ssc[4][MM];
    int g = threadIdx.x >> 6, c = threadIdx.x & 63;
    int n = blockIdx.x * 4 + g;
    bool ok = n < NN;
#pragma unroll
    for (int m = 0; m < MM; m++)
        zsh[g][m][c] = ok ? g_zstack[((size_t)n * MM + m) * CC + c] : 0.f;
    __syncthreads();
#pragma unroll
    for (int m = 0; m < MM; m++) {
        float acc = semb[c];
#pragma unroll 16
        for (int k = 0; k < CC; k++) acc += zsh[g][m][k] * semw[k * CC + c];
        float v = tanhf(acc) * semv[c];
#pragma unroll
        for (int o = 16; o; o >>= 1) v += __shfl_down_sync(0xffffffffu, v, o);
        if ((c & 31) == 0) wred[g][c >> 5] = v;
        __syncthreads();
        if (c == 0) ssc[g][m] = wred[g][0] + wred[g][1];
        __syncthreads();
    }
    if (c == 0) {
        float mx = fmaxf(ssc[g][0], fmaxf(ssc[g][1], ssc[g][2]));
        float e0 = expf(ssc[g][0] - mx), e1 = expf(ssc[g][1] - mx), e2 = expf(ssc[g][2] - mx);
        float inv = 1.f / (e0 + e1 + e2);
        ssc[g][0] = e0 * inv; ssc[g][1] = e1 * inv; ssc[g][2] = e2 * inv;
    }
    __syncthreads();
    if (ok) {
        out[(size_t)n * CC + c] = zsh[g][0][c] * ssc[g][0] + zsh[g][1][c] * ssc[g][1] + zsh[g][2][c] * ssc[g][2];
        if (beta_out != nullptr && c < MM) beta_out[n * MM + c] = ssc[g][c];
    }
}

// ---------------- tiled fused decoder ----------------
__global__ void k_decoder(const float* __restrict__ z,
                          const float* __restrict__ w1, const float* __restrict__ b1,
                          const float* __restrict__ w2, const float* __restrict__ b2,
                          float* __restrict__ xhat) {
    extern __shared__ float sm[];
    float* Ts  = sm;               // [64][65]
    float* Zs  = sm + 4160;        // [64][65]
    float* W1s = sm + 8320;        // [64][64]
    float* W2s = sm + 4160;        // [64][128], overlays phase-1 space
    int nb = blockIdx.x * 64;
    int tid = threadIdx.x;
    int tx = tid & 15, ty = tid >> 4;
#pragma unroll
    for (int i = 0; i < 4; i++) {
        int v = tid + i * 256;
        int row = v >> 4, kq = (v & 15) << 2;
        int gr = nb + row;
        float4 zv = make_float4(0.f, 0.f, 0.f, 0.f);
        if (gr < NN) zv = *(const float4*)(z + (size_t)gr * CC + kq);
        Zs[row * 65 + kq + 0] = zv.x; Zs[row * 65 + kq + 1] = zv.y;
        Zs[row * 65 + kq + 2] = zv.z; Zs[row * 65 + kq + 3] = zv.w;
        *(float4*)&W1s[row * 64 + kq] = *(const float4*)(w1 + row * CC + kq);
    }
    __syncthreads();
    {
        float acc[4][4];
#pragma unroll
        for (int j = 0; j < 4; j++) {
            float bv = b1[tx * 4 + j];
#pragma unroll
            for (int i = 0; i < 4; i++) acc[i][j] = bv;
        }
#pragma unroll 16
        for (int k = 0; k < 64; k++) {
            float a0 = Zs[(ty * 4 + 0) * 65 + k];
            float a1 = Zs[(ty * 4 + 1) * 65 + k];
            float a2 = Zs[(ty * 4 + 2) * 65 + k];
            float a3 = Zs[(ty * 4 + 3) * 65 + k];
            float4 b = *(float4*)&W1s[k * 64 + tx * 4];
            acc[0][0] += a0 * b.x; acc[0][1] += a0 * b.y; acc[0][2] += a0 * b.z; acc[0][3] += a0 * b.w;
            acc[1][0] += a1 * b.x; acc[1][1] += a1 * b.y; acc[1][2] += a1 * b.z; acc[1][3] += a1 * b.w;
            acc[2][0] += a2 * b.x; acc[2][1] += a2 * b.y; acc[2][2] += a2 * b.z; acc[2][3] += a2 * b.w;
            acc[3][0] += a3 * b.x; acc[3][1] += a3 * b.y; acc[3][2] += a3 * b.z; acc[3][3] += a3 * b.w;
        }
#pragma unroll
        for (int i = 0; i < 4; i++)
#pragma unroll
            for (int j = 0; j < 4; j++)
                Ts[(ty * 4 + i) * 65 + tx * 4 + j] = elu1(acc[i][j]);
    }
    __syncthreads();
#pragma unroll
    for (int i = 0; i < 8; i++) {
        int v = tid + i * 256;
        int k = v >> 5, cq = (v & 31) << 2;
        *(float4*)&W2s[k * 128 + cq] = *(const float4*)(w2 + k * FIN + cq);
    }
    __syncthreads();
    {
        float acc[4][8];
#pragma unroll
        for (int j = 0; j < 4; j++) {
            float bva = b2[tx * 4 + j], bvb = b2[64 + tx * 4 + j];
#pragma unroll
            for (int i = 0; i < 4; i++) { acc[i][j] = bva; acc[i][j + 4] = bvb; }
        }
#pragma unroll 8
        for (int k = 0; k < 64; k++) {
            float a0 = Ts[(ty * 4 + 0) * 65 + k];
            float a1 = Ts[(ty * 4 + 1) * 65 + k];
            float a2 = Ts[(ty * 4 + 2) * 65 + k];
            float a3 = Ts[(ty * 4 + 3) * 65 + k];
            float4 ba = *(float4*)&W2s[k * 128 + tx * 4];
            float4 bb = *(float4*)&W2s[k * 128 + 64 + tx * 4];
            acc[0][0] += a0 * ba.x; acc[0][1] += a0 * ba.y; acc[0][2] += a0 * ba.z; acc[0][3] += a0 * ba.w;
            acc[1][0] += a1 * ba.x; acc[1][1] += a1 * ba.y; acc[1][2] += a1 * ba.z; acc[1][3] += a1 * ba.w;
            acc[2][0] += a2 * ba.x; acc[2][1] += a2 * ba.y; acc[2][2] += a2 * ba.z; acc[2][3] += a2 * ba.w;
            acc[3][0] += a3 * ba.x; acc[3][1] += a3 * ba.y; acc[3][2] += a3 * ba.z; acc[3][3] += a3 * ba.w;
            acc[0][4] += a0 * bb.x; acc[0][5] += a0 * bb.y; acc[0][6] += a0 * bb.z; acc[0][7] += a0 * bb.w;
            acc[1][4] += a1 * bb.x; acc[1][5] += a1 * bb.y; acc[1][6] += a1 * bb.z; acc[1][7] += a1 * bb.w;
            acc[2][4] += a2 * bb.x; acc[2][5] += a2 * bb.y; acc[2][6] += a2 * bb.z; acc[2][7] += a2 * bb.w;
            acc[3][4] += a3 * bb.x; acc[3][5] += a3 * bb.y; acc[3][6] += a3 * bb.z; acc[3][7] += a3 * bb.w;
        }
#pragma unroll
        for (int i = 0; i < 4; i++) {
            int gr = nb + ty * 4 + i;
            if (gr < NN) {
                *(float4*)(xhat + (size_t)gr * FIN + tx * 4) =
                    make_float4(acc[i][0], acc[i][1], acc[i][2], acc[i][3]);
                *(float4*)(xhat + (size_t)gr * FIN + 64 + tx * 4) =
                    make_float4(acc[i][4], acc[i][5], acc[i][6], acc[i][7]);
            }
        }
    }
}

// ---------------- host (stream-forked CSR build) ----------------
extern "C" void kernel_launch(void* const* d_in, const int* in_sizes, int n_in,
                              void* d_out, int out_size) {
    const float* x      = (const float*)d_in[0];
    const int*   ei     = (const int*)  d_in[1];   // [M,2,E]
    const float* eattr  = (const float*)d_in[2];   // [M,E,1]
    const float* lin1w  = (const float*)d_in[3];
    const float* a1s    = (const float*)d_in[4];
    const float* a1d    = (const float*)d_in[5];
    const float* l1e    = (const float*)d_in[6];
    const float* a1e    = (const float*)d_in[7];
    const float* b1     = (const float*)d_in[8];
    const float* bn1g   = (const float*)d_in[9];
    const float* bn1b   = (const float*)d_in[10];
    const float* sem1w  = (const float*)d_in[11];
    const float* sem1b  = (const float*)d_in[12];
    const float* sem1v  = (const float*)d_in[13];
    const float* lin2w  = (const float*)d_in[14];
    const float* a2s    = (const float*)d_in[15];
    const float* a2d    = (const float*)d_in[16];
    const float* l2e    = (const float*)d_in[17];
    const float* a2e    = (const float*)d_in[18];
    const float* b2     = (const float*)d_in[19];
    const float* bn2g   = (const float*)d_in[20];
    const float* bn2b   = (const float*)d_in[21];
    const float* sem2w  = (const float*)d_in[22];
    const float* sem2b  = (const float*)d_in[23];
    const float* sem2v  = (const float*)d_in[24];
    const float* dec1w  = (const float*)d_in[25];
    const float* dec1b  = (const float*)d_in[26];
    const float* dec2w  = (const float*)d_in[27];
    const float* dec2b  = (const float*)d_in[28];

    float* z_out    = (float*)d_out;             // [N, C2]
    float* xhat     = z_out + NN * CC;           // [N, IN]
    float* beta_out = xhat + NN * FIN;           // [N, M]

    float* houtp = nullptr;
    cudaGetSymbolAddress((void**)&houtp, g_hout);
    float *edot1p = nullptr, *edot2p = nullptr, *aff1p = nullptr, *aff2p = nullptr;
    cudaGetSymbolAddress((void**)&edot1p, g_edot1);
    cudaGetSymbolAddress((void**)&edot2p, g_edot2);
    cudaGetSymbolAddress((void**)&aff1p, g_aff1);
    cudaGetSymbolAddress((void**)&aff2p, g_aff2);

    const int EB = (EE + 255) / 256;
    const int NB64 = (NN + 63) / 64;
    const int NB128 = (NN + 127) / 128;

    int smem2 = (64 * 68 + 64 * 64) * 4;    // 33792

    static cudaStream_t s2;
    static cudaEvent_t evA, evB;
    static bool init_done = false;
    if (!init_done) {
        cudaFuncSetAttribute(k_sgemm<CC, CC, 64, 1>, cudaFuncAttributeMaxDynamicSharedMemorySize, smem2);
        cudaFuncSetAttribute(k_decoder, cudaFuncAttributeMaxDynamicSharedMemorySize, 12416 * 4);
        cudaStreamCreateWithFlags(&s2, cudaStreamNonBlocking);
        cudaEventCreateWithFlags(&evA, cudaEventDisableTiming);
        cudaEventCreateWithFlags(&evB, cudaEventDisableTiming);
        init_done = true;
    }

    // ---- fork: CSR build + BN on s2, concurrent with sgemm1 on origin stream ----
    cudaEventRecord(evA, 0);
    cudaStreamWaitEvent(s2, evA, 0);
    k_zero1<<<(MM * NN + 255) / 256, 256, 0, s2>>>();
    k_build<<<dim3(EB, MM), 256, 0, s2>>>(ei, eattr);
    k_scan<<<MM, 1024, 0, s2>>>();
    k_scatter<<<dim3(EB, MM), 256, 0, s2>>>(ei);
    k_bnfin<HH, CC><<<1, MM * HH * 32, 0, s2>>>(l1e, a1e, bn1g, bn1b, edot1p, aff1p);
    k_bnfin<1, CC><<<1, MM * 32, 0, s2>>>(l2e, a2e, bn2g, bn2b, edot2p, aff2p);
    cudaEventRecord(evB, s2);

    k_sgemm1<FIN, HH * CC, HH><<<dim3(2, NB128, MM), 256>>>(x, lin1w, a1s, a1d);
    cudaStreamWaitEvent(0, evB, 0);

    // ---- HAN layer 1 (heads = 4) ----
    k_gat4<<<dim3(NN / 8, MM), 256>>>(b1);
    k_semantic<<<(NN + 3) / 4, 256>>>(sem1w, sem1b, sem1v, houtp, nullptr);

    // ---- HAN layer 2 (heads = 1) ----
    k_sgemm<CC, CC, 64, 1><<<dim3(1, NB64, MM), 256, smem2>>>(houtp, lin2w, a2s, a2d);
    k_gat1<<<dim3(NN / 32, MM), 256>>>(b2);
    k_semantic<<<(NN + 3) / 4, 256>>>(sem2w, sem2b, sem2v, z_out, beta_out);

    // ---- decoder ----
    k_decoder<<<NB64, 256, 12416 * 4>>>(z_out, dec1w, dec1b, dec2w, dec2b, xhat);
}